// round 2
// baseline (speedup 1.0000x reference)
#include <cuda_runtime.h>
#include <math.h>

#define Bb 4
#define Ss 1024
#define Ee 256
#define Hh 8
#define Dd 32
#define TOK (Bb*Ss)
#define QB 32

// ---------------- scratch (no allocations allowed) ----------------
__device__ float g_Q[TOK*Ee];
__device__ float g_K[TOK*Ee];
__device__ float g_V[TOK*Ee];
__device__ float g_H[TOK*(Ee/2)];
__device__ float g_O[TOK*2*Hh];
__device__ float g_A[TOK*Ee];

// ---------------- generic tiled SGEMM: C = A[MxK] @ B[KxN] (+bias)(+gelu) ---
// EPI: 0 = none, 1 = bias, 2 = bias+gelu(exact erf)
template<int EPI>
__global__ __launch_bounds__(256)
void gemm_kernel(const float* __restrict__ A, const float* __restrict__ B,
                 const float* __restrict__ bias, float* __restrict__ C,
                 int M, int N, int K)
{
    __shared__ float As[16*64];
    __shared__ float Bs[16*64];
    const int tid = threadIdx.x;
    const int tx = tid & 15;        // n dir
    const int ty = tid >> 4;        // m dir
    const int m0 = blockIdx.y * 64;
    const int n0 = blockIdx.x * 64;

    const int arow = tid >> 2;          // 0..63
    const int ak4  = (tid & 3) * 4;     // 0..12
    const int brow = tid >> 4;          // 0..15
    const int bn4  = (tid & 15) * 4;    // 0..60

    float acc[4][4] = {};

    for (int k0 = 0; k0 < K; k0 += 16) {
        // load A tile (64x16) transposed into As[k][m]
        float4 av = *(const float4*)&A[(size_t)(m0 + arow) * K + k0 + ak4];
        As[(ak4+0)*64 + arow] = av.x;
        As[(ak4+1)*64 + arow] = av.y;
        As[(ak4+2)*64 + arow] = av.z;
        As[(ak4+3)*64 + arow] = av.w;
        // load B tile (16x64) into Bs[k][n] with guard
        float4 bv = make_float4(0.f,0.f,0.f,0.f);
        if (n0 + bn4 < N)
            bv = *(const float4*)&B[(size_t)(k0 + brow) * N + n0 + bn4];
        *(float4*)&Bs[brow*64 + bn4] = bv;
        __syncthreads();

        #pragma unroll
        for (int kk = 0; kk < 16; ++kk) {
            float4 ar = *(const float4*)&As[kk*64 + ty*4];
            float4 br = *(const float4*)&Bs[kk*64 + tx*4];
            float a4[4] = {ar.x, ar.y, ar.z, ar.w};
            float b4[4] = {br.x, br.y, br.z, br.w};
            #pragma unroll
            for (int i = 0; i < 4; ++i)
                #pragma unroll
                for (int j = 0; j < 4; ++j)
                    acc[i][j] += a4[i] * b4[j];
        }
        __syncthreads();
    }

    #pragma unroll
    for (int i = 0; i < 4; ++i) {
        int m = m0 + ty*4 + i;
        #pragma unroll
        for (int j = 0; j < 4; ++j) {
            int n = n0 + tx*4 + j;
            if (n < N) {
                float v = acc[i][j];
                if (EPI >= 1) v += bias[n];
                if (EPI == 2) v = 0.5f * v * (1.0f + erff(v * 0.70710678118654752440f));
                C[(size_t)m * N + n] = v;
            }
        }
    }
}

// ---------------- fused deformable attention ----------------
// grid: Bb*Hh*(Ss/QB) CTAs, 256 threads
// smem: T[QB][Ss] | Qe[QB][40] | Ks[64][33] (reused as Vs) | wx[QB] | rsum[QB] | ax[QB]
__global__ __launch_bounds__(256)
void attn_kernel(const float* __restrict__ Q, const float* __restrict__ K,
                 const float* __restrict__ V, const float* __restrict__ OFF,
                 float* __restrict__ Aout)
{
    extern __shared__ float sm[];
    float* T    = sm;                     // QB*Ss
    float* Qe   = T + QB*Ss;              // QB*40
    float* Ks   = Qe + QB*40;             // 64*33
    float* wxs  = Ks + 64*33;             // QB
    float* rsum = wxs + QB;               // QB
    int*   axs  = (int*)(rsum + QB);      // QB

    const int tid = threadIdx.x;
    const int nq  = Ss / QB;
    const int bh  = blockIdx.x / nq;
    const int q0  = (blockIdx.x % nq) * QB;
    const int b   = bh / Hh;
    const int h   = bh % Hh;
    const float scale = 0.17677669529663689f;  // 1/sqrt(32)

    const float* Qbh = Q + (size_t)b*Ss*Ee + h*Dd;
    const float* Kbh = K + (size_t)b*Ss*Ee + h*Dd;
    const float* Vbh = V + (size_t)b*Ss*Ee + h*Dd;

    // ---- Phase 0: build Qeff (row-blended, scaled), stash wx/ax ----
    {
        const int d = tid & 31;
        #pragma unroll
        for (int it = 0; it < QB/8; ++it) {
            int q = (tid >> 5) + it*8;
            int i = q0 + q;
            float ox = OFF[((size_t)(b*Ss + i)*Hh + h)*2 + 0];
            float oy = OFF[((size_t)(b*Ss + i)*Hh + h)*2 + 1];
            float fy = floorf(oy);
            float wy = oy - fy;
            int y0 = i + (int)fy;
            int y1 = y0 + 1;
            float qv = 0.f;
            if (y0 >= 0 && y0 < Ss) qv += (1.f - wy) * Qbh[(size_t)y0*Ee + d];
            if (y1 >= 0 && y1 < Ss) qv += wy * Qbh[(size_t)y1*Ee + d];
            Qe[q*40 + d] = qv * scale;
            if (d == 0) {
                float fx = floorf(ox);
                wxs[q] = ox - fx;
                axs[q] = (int)fx;
            }
        }
    }
    __syncthreads();

    // ---- Phase 1: T[q][c] = Qeff[q] . K[c] ----
    {
        const int cl = tid & 63;
        const int qg = tid >> 6;   // 4 groups x 8 queries
        for (int ct = 0; ct < Ss/64; ++ct) {
            const int c0 = ct * 64;
            #pragma unroll
            for (int l = 0; l < 2; ++l) {
                int idx = tid + l*256;
                int r = idx >> 3, d4 = (idx & 7) * 4;
                float4 kv = *(const float4*)&Kbh[(size_t)(c0 + r)*Ee + d4];
                Ks[r*33 + d4 + 0] = kv.x;
                Ks[r*33 + d4 + 1] = kv.y;
                Ks[r*33 + d4 + 2] = kv.z;
                Ks[r*33 + d4 + 3] = kv.w;
            }
            __syncthreads();
            float kreg[32];
            #pragma unroll
            for (int d = 0; d < 32; ++d) kreg[d] = Ks[cl*33 + d];
            #pragma unroll
            for (int qq = 0; qq < 8; ++qq) {
                int q = qg*8 + qq;
                float a0 = 0.f, a1 = 0.f;
                #pragma unroll
                for (int d = 0; d < 32; d += 2) {
                    a0 += Qe[q*40 + d]     * kreg[d];
                    a1 += Qe[q*40 + d + 1] * kreg[d + 1];
                }
                T[q*Ss + c0 + cl] = a0 + a1;
            }
            __syncthreads();
        }
    }

    // ---- Phase 2: shift/blend + softmax (warp per query row) ----
    {
        const int lane = tid & 31;
        const int w = tid >> 5;
        #pragma unroll
        for (int it = 0; it < QB/8; ++it) {
            int q = w + it*8;
            float wx = wxs[q];
            int ax = axs[q];
            float* Tq = T + q*Ss;
            float dv[32];
            float m = -1e30f;
            #pragma unroll
            for (int jj = 0; jj < 32; ++jj) {
                int j = lane + jj*32;
                int c0 = j + ax, c1 = c0 + 1;
                float t0 = (c0 >= 0 && c0 < Ss) ? Tq[c0] : 0.f;
                float t1 = (c1 >= 0 && c1 < Ss) ? Tq[c1] : 0.f;
                float v = (1.f - wx)*t0 + wx*t1;
                dv[jj] = v;
                m = fmaxf(m, v);
            }
            #pragma unroll
            for (int o = 16; o; o >>= 1) m = fmaxf(m, __shfl_xor_sync(0xffffffffu, m, o));
            float s = 0.f;
            #pragma unroll
            for (int jj = 0; jj < 32; ++jj) { float e = __expf(dv[jj] - m); dv[jj] = e; s += e; }
            #pragma unroll
            for (int o = 16; o; o >>= 1) s += __shfl_xor_sync(0xffffffffu, s, o);
            #pragma unroll
            for (int jj = 0; jj < 32; ++jj) Tq[lane + jj*32] = dv[jj];
            if (lane == 0) rsum[q] = s;
        }
    }
    __syncthreads();

    // ---- Phase 3: out[q][d] = (1/rsum[q]) * sum_j P[q][j] * V[j][d] ----
    {
        const int d = tid & 31;
        const int qg = tid >> 5;   // 8 groups x 4 queries
        float acc[4] = {0.f, 0.f, 0.f, 0.f};
        float* Vs = Ks;            // reuse staging buffer
        for (int jt = 0; jt < Ss/64; ++jt) {
            const int j0 = jt * 64;
            #pragma unroll
            for (int l = 0; l < 2; ++l) {
                int idx = tid + l*256;
                int r = idx >> 3, d4 = (idx & 7) * 4;
                float4 vv = *(const float4*)&Vbh[(size_t)(j0 + r)*Ee + d4];
                Vs[r*33 + d4 + 0] = vv.x;
                Vs[r*33 + d4 + 1] = vv.y;
                Vs[r*33 + d4 + 2] = vv.z;
                Vs[r*33 + d4 + 3] = vv.w;
            }
            __syncthreads();
            #pragma unroll
            for (int jl = 0; jl < 64; jl += 4) {
                float v0 = Vs[(jl+0)*33 + d];
                float v1 = Vs[(jl+1)*33 + d];
                float v2 = Vs[(jl+2)*33 + d];
                float v3 = Vs[(jl+3)*33 + d];
                #pragma unroll
                for (int qq = 0; qq < 4; ++qq) {
                    const float4 p = *(const float4*)&T[(qg*4+qq)*Ss + j0 + jl];
                    acc[qq] += p.x*v0 + p.y*v1 + p.z*v2 + p.w*v3;
                }
            }
            __syncthreads();
        }
        #pragma unroll
        for (int qq = 0; qq < 4; ++qq) {
            int q = qg*4 + qq;
            int i = q0 + q;
            Aout[((size_t)b*Ss + i)*Ee + h*Dd + d] = acc[qq] * (1.f / rsum[q]);
        }
    }
}

// ---------------- host launch ----------------
extern "C" void kernel_launch(void* const* d_in, const int* in_sizes, int n_in,
                              void* d_out, int out_size)
{
    (void)in_sizes; (void)n_in; (void)out_size;
    const float* x      = (const float*)d_in[0];
    const float* Wq     = (const float*)d_in[1];
    const float* Wk     = (const float*)d_in[2];
    const float* Wv     = (const float*)d_in[3];
    const float* W_off1 = (const float*)d_in[4];
    const float* b_off1 = (const float*)d_in[5];
    const float* W_off2 = (const float*)d_in[6];
    const float* b_off2 = (const float*)d_in[7];
    const float* W_out  = (const float*)d_in[8];
    const float* b_out  = (const float*)d_in[9];
    float* out = (float*)d_out;

    float *gQ, *gK, *gV, *gH, *gO, *gA;
    cudaGetSymbolAddress((void**)&gQ, g_Q);
    cudaGetSymbolAddress((void**)&gK, g_K);
    cudaGetSymbolAddress((void**)&gV, g_V);
    cudaGetSymbolAddress((void**)&gH, g_H);
    cudaGetSymbolAddress((void**)&gO, g_O);
    cudaGetSymbolAddress((void**)&gA, g_A);

    const int attn_smem = (QB*Ss + QB*40 + 64*33 + QB + QB + QB) * (int)sizeof(float);
    cudaFuncSetAttribute(attn_kernel, cudaFuncAttributeMaxDynamicSharedMemorySize, attn_smem);

    dim3 blk(256);
    dim3 g256(4, TOK/64);   // N=256
    dim3 g128(2, TOK/64);   // N=128
    dim3 g16 (1, TOK/64);   // N=16

    gemm_kernel<0><<<g256, blk>>>(x,  Wq,     nullptr, gQ, TOK, Ee,   Ee);
    gemm_kernel<0><<<g256, blk>>>(x,  Wk,     nullptr, gK, TOK, Ee,   Ee);
    gemm_kernel<0><<<g256, blk>>>(x,  Wv,     nullptr, gV, TOK, Ee,   Ee);
    gemm_kernel<2><<<g128, blk>>>(x,  W_off1, b_off1,  gH, TOK, Ee/2, Ee);
    gemm_kernel<1><<<g16,  blk>>>(gH, W_off2, b_off2,  gO, TOK, 2*Hh, Ee/2);

    attn_kernel<<<Bb*Hh*(Ss/QB), blk, attn_smem>>>(gQ, gK, gV, gO, gA);

    gemm_kernel<1><<<g256, blk>>>(gA, W_out,  b_out,   out, TOK, Ee,  Ee);
}

// round 3
// speedup vs baseline: 1.3482x; 1.3482x over previous
#include <cuda_runtime.h>
#include <math.h>

#define Bb 4
#define Ss 1024
#define Ee 256
#define Hh 8
#define Dd 32
#define TOK (Bb*Ss)
#define QB 32
#define RS 768          // fused QKV row stride
#define CT 256          // attention col tile
#define TP 1032         // padded T row (kills P-read bank conflicts)

// ---------------- scratch ----------------
__device__ float g_QKV[TOK*RS];
__device__ float g_H[TOK*(Ee/2)];
__device__ float g_O[TOK*2*Hh];
__device__ float g_A[TOK*Ee];

// ---------------- fused QKV + MLP1 GEMM ----------------
// grid (14, TOK/64): nb 0..11 -> QKV (no epi), nb 12..13 -> MLP1 (bias+gelu)
__global__ __launch_bounds__(256)
void qkv_mlp_kernel(const float* __restrict__ x,
                    const float* __restrict__ Wq, const float* __restrict__ Wk,
                    const float* __restrict__ Wv, const float* __restrict__ W1,
                    const float* __restrict__ b1,
                    float* __restrict__ QKV, float* __restrict__ Hout)
{
    __shared__ float As[16*64];
    __shared__ float Bs[16*64];
    const int tid = threadIdx.x;
    const int tx = tid & 15, ty = tid >> 4;
    const int nb = blockIdx.x;
    const int m0 = blockIdx.y * 64;

    const float* Bp; int bn0, BN;
    if (nb < 12) { Bp = (nb < 4 ? Wq : (nb < 8 ? Wk : Wv)); bn0 = (nb & 3) * 64; BN = 256; }
    else         { Bp = W1; bn0 = (nb - 12) * 64; BN = 128; }

    const int arow = tid >> 2, ak4 = (tid & 3) * 4;
    const int brow = tid >> 4, bn4 = (tid & 15) * 4;

    float acc[4][4] = {};
    float4 aPre = *(const float4*)&x[(size_t)(m0 + arow) * 256 + ak4];
    float4 bPre = *(const float4*)&Bp[(size_t)brow * BN + bn0 + bn4];

    for (int k0 = 0; k0 < 256; k0 += 16) {
        As[(ak4+0)*64 + arow] = aPre.x;
        As[(ak4+1)*64 + arow] = aPre.y;
        As[(ak4+2)*64 + arow] = aPre.z;
        As[(ak4+3)*64 + arow] = aPre.w;
        *(float4*)&Bs[brow*64 + bn4] = bPre;
        __syncthreads();
        if (k0 + 16 < 256) {
            aPre = *(const float4*)&x[(size_t)(m0 + arow) * 256 + k0 + 16 + ak4];
            bPre = *(const float4*)&Bp[(size_t)(k0 + 16 + brow) * BN + bn0 + bn4];
        }
        #pragma unroll
        for (int kk = 0; kk < 16; ++kk) {
            float4 ar = *(const float4*)&As[kk*64 + ty*4];
            float4 br = *(const float4*)&Bs[kk*64 + tx*4];
            float a4[4] = {ar.x, ar.y, ar.z, ar.w};
            float b4[4] = {br.x, br.y, br.z, br.w};
            #pragma unroll
            for (int i = 0; i < 4; ++i)
                #pragma unroll
                for (int j = 0; j < 4; ++j)
                    acc[i][j] += a4[i] * b4[j];
        }
        __syncthreads();
    }

    if (nb < 12) {
        #pragma unroll
        for (int i = 0; i < 4; ++i) {
            int m = m0 + ty*4 + i;
            #pragma unroll
            for (int j = 0; j < 4; ++j)
                QKV[(size_t)m * RS + nb*64 + tx*4 + j] = acc[i][j];
        }
    } else {
        #pragma unroll
        for (int i = 0; i < 4; ++i) {
            int m = m0 + ty*4 + i;
            #pragma unroll
            for (int j = 0; j < 4; ++j) {
                int n = (nb - 12)*64 + tx*4 + j;
                float v = acc[i][j] + b1[n];
                v = 0.5f * v * (1.0f + erff(v * 0.70710678118654752440f));
                Hout[(size_t)m * 128 + n] = v;
            }
        }
    }
}

// ---------------- generic GEMM (MLP2, out-proj): C = A@B + bias ----------------
__global__ __launch_bounds__(256)
void gemm_kernel(const float* __restrict__ A, const float* __restrict__ B,
                 const float* __restrict__ bias, float* __restrict__ C,
                 int M, int N, int K)
{
    __shared__ float As[16*64];
    __shared__ float Bs[16*64];
    const int tid = threadIdx.x;
    const int tx = tid & 15, ty = tid >> 4;
    const int m0 = blockIdx.y * 64;
    const int n0 = blockIdx.x * 64;

    const int arow = tid >> 2, ak4 = (tid & 3) * 4;
    const int brow = tid >> 4, bn4 = (tid & 15) * 4;

    float acc[4][4] = {};
    float4 aPre = *(const float4*)&A[(size_t)(m0 + arow) * K + ak4];
    float4 bPre = make_float4(0.f,0.f,0.f,0.f);
    if (n0 + bn4 < N) bPre = *(const float4*)&B[(size_t)brow * N + n0 + bn4];

    for (int k0 = 0; k0 < K; k0 += 16) {
        As[(ak4+0)*64 + arow] = aPre.x;
        As[(ak4+1)*64 + arow] = aPre.y;
        As[(ak4+2)*64 + arow] = aPre.z;
        As[(ak4+3)*64 + arow] = aPre.w;
        *(float4*)&Bs[brow*64 + bn4] = bPre;
        __syncthreads();
        if (k0 + 16 < K) {
            aPre = *(const float4*)&A[(size_t)(m0 + arow) * K + k0 + 16 + ak4];
            if (n0 + bn4 < N) bPre = *(const float4*)&B[(size_t)(k0 + 16 + brow) * N + n0 + bn4];
        }
        #pragma unroll
        for (int kk = 0; kk < 16; ++kk) {
            float4 ar = *(const float4*)&As[kk*64 + ty*4];
            float4 br = *(const float4*)&Bs[kk*64 + tx*4];
            float a4[4] = {ar.x, ar.y, ar.z, ar.w};
            float b4[4] = {br.x, br.y, br.z, br.w};
            #pragma unroll
            for (int i = 0; i < 4; ++i)
                #pragma unroll
                for (int j = 0; j < 4; ++j)
                    acc[i][j] += a4[i] * b4[j];
        }
        __syncthreads();
    }

    #pragma unroll
    for (int i = 0; i < 4; ++i) {
        int m = m0 + ty*4 + i;
        #pragma unroll
        for (int j = 0; j < 4; ++j) {
            int n = n0 + tx*4 + j;
            if (n < N) C[(size_t)m * N + n] = acc[i][j] + bias[n];
        }
    }
}

// ---------------- fused deformable attention ----------------
__global__ __launch_bounds__(256, 1)
void attn_kernel(const float* __restrict__ QKV, const float* __restrict__ OFF,
                 float* __restrict__ Aout)
{
    extern __shared__ float sm[];
    float* T    = sm;                  // QB * TP
    float* Ks   = T + QB*TP;           // CT * 32   (K tile, reused as V tile)
    float* Qe   = Ks + CT*32;          // 32 * 32
    float* wxs  = Qe + 32*32;
    float* rsum = wxs + QB;
    int*   axs  = (int*)(rsum + QB);

    const int tid = threadIdx.x;
    const int nq  = Ss / QB;
    const int bh  = blockIdx.x / nq;
    const int q0  = (blockIdx.x % nq) * QB;
    const int b   = bh / Hh;
    const int h   = bh % Hh;
    const float scale = 0.17677669529663689f;

    const float* Qb = QKV + (size_t)b*Ss*RS + h*Dd;
    const float* Kb = Qb + 256;
    const float* Vb = Qb + 512;

    // ---- Phase 0: Qeff (row-blended, pre-scaled) + wx/ax ----
    {
        const int d = tid & 31;
        const int qq = tid >> 5;
        #pragma unroll
        for (int it = 0; it < 4; ++it) {
            int q = qq + it*8;
            int i = q0 + q;
            float ox = OFF[((size_t)(b*Ss + i)*Hh + h)*2 + 0];
            float oy = OFF[((size_t)(b*Ss + i)*Hh + h)*2 + 1];
            float fy = floorf(oy);
            float wy = oy - fy;
            int y0 = i + (int)fy, y1 = y0 + 1;
            float qv = 0.f;
            if (y0 >= 0 && y0 < Ss) qv += (1.f - wy) * Qb[(size_t)y0*RS + d];
            if (y1 >= 0 && y1 < Ss) qv += wy * Qb[(size_t)y1*RS + d];
            Qe[q*32 + d] = qv * scale;
            if (d == 0) { float fx = floorf(ox); wxs[q] = ox - fx; axs[q] = (int)fx; }
        }
    }
    __syncthreads();

    // ---- Phase 1: T = Qeff . K^T  (register-blocked 8q x 4c, swizzled K tile) ----
    {
        const int cg = tid & 63;
        const int qg = tid >> 6;
        const int swz = cg & 7;
        float acc[8][4];
        float4 pre[8];
        #pragma unroll
        for (int l = 0; l < 8; ++l) {
            int idx = tid + l*256;
            int c = idx >> 3, t = idx & 7;
            pre[l] = *(const float4*)&Kb[(size_t)c*RS + t*4];
        }
        for (int ct = 0; ct < Ss/CT; ++ct) {
            #pragma unroll
            for (int l = 0; l < 8; ++l) {
                int idx = tid + l*256;
                int c = idx >> 3, t = idx & 7;
                *(float4*)&Ks[c*32 + ((t ^ (c & 7)) << 2)] = pre[l];
            }
            __syncthreads();
            if (ct + 1 < Ss/CT) {
                #pragma unroll
                for (int l = 0; l < 8; ++l) {
                    int idx = tid + l*256;
                    int c = idx >> 3, t = idx & 7;
                    pre[l] = *(const float4*)&Kb[(size_t)((ct+1)*CT + c)*RS + t*4];
                }
            }
            #pragma unroll
            for (int i = 0; i < 8; ++i)
                #pragma unroll
                for (int j = 0; j < 4; ++j) acc[i][j] = 0.f;
            #pragma unroll
            for (int t = 0; t < 8; ++t) {
                float4 Kf[4];
                #pragma unroll
                for (int j = 0; j < 4; ++j)
                    Kf[j] = *(const float4*)&Ks[(cg + 64*j)*32 + ((t ^ swz) << 2)];
                #pragma unroll
                for (int i = 0; i < 8; ++i) {
                    float4 Qf = *(const float4*)&Qe[(qg*8 + i)*32 + t*4];
                    #pragma unroll
                    for (int j = 0; j < 4; ++j)
                        acc[i][j] += Qf.x*Kf[j].x + Qf.y*Kf[j].y + Qf.z*Kf[j].z + Qf.w*Kf[j].w;
                }
            }
            #pragma unroll
            for (int i = 0; i < 8; ++i)
                #pragma unroll
                for (int j = 0; j < 4; ++j)
                    T[(qg*8 + i)*TP + ct*CT + cg + 64*j] = acc[i][j];
            __syncthreads();
        }
    }

    // ---- Phase 2: shift/blend + softmax (warp per query) ----
    {
        const int lane = tid & 31;
        const int w = tid >> 5;
        #pragma unroll
        for (int it = 0; it < 4; ++it) {
            int q = w + it*8;
            float wx = wxs[q];
            int ax = axs[q];
            float* Tq = T + q*TP;
            float dv[32];
            float m = -1e30f;
            #pragma unroll
            for (int jj = 0; jj < 32; ++jj) {
                int j = lane + jj*32;
                int c0 = j + ax, c1 = c0 + 1;
                float t0 = (c0 >= 0 && c0 < Ss) ? Tq[c0] : 0.f;
                float t1 = (c1 >= 0 && c1 < Ss) ? Tq[c1] : 0.f;
                float v = (1.f - wx)*t0 + wx*t1;
                dv[jj] = v;
                m = fmaxf(m, v);
            }
            #pragma unroll
            for (int o = 16; o; o >>= 1) m = fmaxf(m, __shfl_xor_sync(0xffffffffu, m, o));
            float s = 0.f;
            #pragma unroll
            for (int jj = 0; jj < 32; ++jj) { float e = __expf(dv[jj] - m); dv[jj] = e; s += e; }
            #pragma unroll
            for (int o = 16; o; o >>= 1) s += __shfl_xor_sync(0xffffffffu, s, o);
            #pragma unroll
            for (int jj = 0; jj < 32; ++jj) Tq[lane + jj*32] = dv[jj];
            if (lane == 0) rsum[q] = s;
        }
    }
    __syncthreads();

    // ---- Phase 3: out = P.V (thread = one query x 4 dims, swizzled V tile) ----
    {
        const int dc = tid & 7;
        const int q  = tid >> 3;
        float4 acc = make_float4(0.f, 0.f, 0.f, 0.f);
        float4 pre[8];
        #pragma unroll
        for (int l = 0; l < 8; ++l) {
            int idx = tid + l*256;
            int c = idx >> 3, t = idx & 7;
            pre[l] = *(const float4*)&Vb[(size_t)c*RS + t*4];
        }
        for (int jt = 0; jt < Ss/CT; ++jt) {
            #pragma unroll
            for (int l = 0; l < 8; ++l) {
                int idx = tid + l*256;
                int c = idx >> 3, t = idx & 7;
                *(float4*)&Ks[c*32 + ((t ^ (c & 7)) << 2)] = pre[l];
            }
            __syncthreads();
            if (jt + 1 < Ss/CT) {
                #pragma unroll
                for (int l = 0; l < 8; ++l) {
                    int idx = tid + l*256;
                    int c = idx >> 3, t = idx & 7;
                    pre[l] = *(const float4*)&Vb[(size_t)((jt+1)*CT + c)*RS + t*4];
                }
            }
            const float* Tq = T + q*TP + jt*CT;
            #pragma unroll 8
            for (int jj = 0; jj < CT; jj += 4) {
                float4 P = *(const float4*)&Tq[jj];
                float pv[4] = {P.x, P.y, P.z, P.w};
                #pragma unroll
                for (int u = 0; u < 4; ++u) {
                    int j = jj + u;
                    float4 Vf = *(const float4*)&Ks[j*32 + ((dc ^ (j & 7)) << 2)];
                    acc.x += pv[u]*Vf.x; acc.y += pv[u]*Vf.y;
                    acc.z += pv[u]*Vf.z; acc.w += pv[u]*Vf.w;
                }
            }
            __syncthreads();
        }
        float inv = 1.f / rsum[q];
        int i = q0 + q;
        float4 o = make_float4(acc.x*inv, acc.y*inv, acc.z*inv, acc.w*inv);
        *(float4*)&Aout[((size_t)b*Ss + i)*Ee + h*Dd + dc*4] = o;
    }
}

// ---------------- host launch ----------------
extern "C" void kernel_launch(void* const* d_in, const int* in_sizes, int n_in,
                              void* d_out, int out_size)
{
    (void)in_sizes; (void)n_in; (void)out_size;
    const float* x      = (const float*)d_in[0];
    const float* Wq     = (const float*)d_in[1];
    const float* Wk     = (const float*)d_in[2];
    const float* Wv     = (const float*)d_in[3];
    const float* W_off1 = (const float*)d_in[4];
    const float* b_off1 = (const float*)d_in[5];
    const float* W_off2 = (const float*)d_in[6];
    const float* b_off2 = (const float*)d_in[7];
    const float* W_out  = (const float*)d_in[8];
    const float* b_out  = (const float*)d_in[9];
    float* out = (float*)d_out;

    float *gQKV, *gH, *gO, *gA;
    cudaGetSymbolAddress((void**)&gQKV, g_QKV);
    cudaGetSymbolAddress((void**)&gH,   g_H);
    cudaGetSymbolAddress((void**)&gO,   g_O);
    cudaGetSymbolAddress((void**)&gA,   g_A);

    const int attn_smem = (QB*TP + CT*32 + 32*32 + QB + QB + QB) * (int)sizeof(float);
    cudaFuncSetAttribute(attn_kernel, cudaFuncAttributeMaxDynamicSharedMemorySize, attn_smem);

    dim3 blk(256);

    qkv_mlp_kernel<<<dim3(14, TOK/64), blk>>>(x, Wq, Wk, Wv, W_off1, b_off1, gQKV, gH);
    gemm_kernel<<<dim3(1, TOK/64), blk>>>(gH, W_off2, b_off2, gO, TOK, 2*Hh, Ee/2);
    attn_kernel<<<Bb*Hh*(Ss/QB), blk, attn_smem>>>(gQKV, gO, gA);
    gemm_kernel<<<dim3(4, TOK/64), blk>>>(gA, W_out, b_out, out, TOK, Ee, Ee);
}

// round 9
// speedup vs baseline: 1.9247x; 1.4276x over previous
#include <cuda_runtime.h>
#include <math.h>

#define Bb 4
#define Ss 1024
#define Ee 256
#define Hh 8
#define Dd 32
#define TOK (Bb*Ss)
#define QB 32
#define RS 768          // fused QKV row stride
#define CT 256          // attention col tile
#define TP 1032         // padded T row
#define KSST 36         // K-tile smem stride (floats): float4-aligned, conflict-free frags
#define VTST 260        // transposed V-tile stride
#define QEST 33         // Qe stride
#define REDW 1056       // 32*33 per-warp reduction slab

// ---------------- scratch ----------------
__device__ float g_QKV[TOK*RS];
__device__ float g_H[TOK*(Ee/2)];
__device__ float g_O[TOK*2*Hh];
__device__ float g_A[TOK*Ee];

// ---------------- tf32 helpers ----------------
__device__ __forceinline__ void tf32split(float x, unsigned &hi, unsigned &lo) {
    unsigned h; asm("cvt.rna.tf32.f32 %0, %1;" : "=r"(h) : "f"(x));
    float r = x - __uint_as_float(h);
    unsigned l; asm("cvt.rna.tf32.f32 %0, %1;" : "=r"(l) : "f"(r));
    hi = h; lo = l;
}

__device__ __forceinline__ void mma_tf32(float* d, const unsigned* a, unsigned b0, unsigned b1) {
    asm volatile("mma.sync.aligned.m16n8k8.row.col.f32.tf32.tf32.f32 "
        "{%0,%1,%2,%3},{%4,%5,%6,%7},{%8,%9},{%0,%1,%2,%3};"
        : "+f"(d[0]), "+f"(d[1]), "+f"(d[2]), "+f"(d[3])
        : "r"(a[0]), "r"(a[1]), "r"(a[2]), "r"(a[3]), "r"(b0), "r"(b1));
}

// ---------------- fused QKV + MLP1 GEMM ----------------
__global__ __launch_bounds__(256)
void qkv_mlp_kernel(const float* __restrict__ x,
                    const float* __restrict__ Wq, const float* __restrict__ Wk,
                    const float* __restrict__ Wv, const float* __restrict__ W1,
                    const float* __restrict__ b1,
                    float* __restrict__ QKV, float* __restrict__ Hout)
{
    __shared__ float As[16*64];
    __shared__ float Bs[16*64];
    const int tid = threadIdx.x;
    const int tx = tid & 15, ty = tid >> 4;
    const int nb = blockIdx.x;
    const int m0 = blockIdx.y * 64;

    const float* Bp; int bn0, BN;
    if (nb < 12) { Bp = (nb < 4 ? Wq : (nb < 8 ? Wk : Wv)); bn0 = (nb & 3) * 64; BN = 256; }
    else         { Bp = W1; bn0 = (nb - 12) * 64; BN = 128; }

    const int arow = tid >> 2, ak4 = (tid & 3) * 4;
    const int brow = tid >> 4, bn4 = (tid & 15) * 4;

    float acc[4][4] = {};
    float4 aPre = *(const float4*)&x[(size_t)(m0 + arow) * 256 + ak4];
    float4 bPre = *(const float4*)&Bp[(size_t)brow * BN + bn0 + bn4];

    for (int k0 = 0; k0 < 256; k0 += 16) {
        As[(ak4+0)*64 + arow] = aPre.x;
        As[(ak4+1)*64 + arow] = aPre.y;
        As[(ak4+2)*64 + arow] = aPre.z;
        As[(ak4+3)*64 + arow] = aPre.w;
        *(float4*)&Bs[brow*64 + bn4] = bPre;
        __syncthreads();
        if (k0 + 16 < 256) {
            aPre = *(const float4*)&x[(size_t)(m0 + arow) * 256 + k0 + 16 + ak4];
            bPre = *(const float4*)&Bp[(size_t)(k0 + 16 + brow) * BN + bn0 + bn4];
        }
        #pragma unroll
        for (int kk = 0; kk < 16; ++kk) {
            float4 ar = *(const float4*)&As[kk*64 + ty*4];
            float4 br = *(const float4*)&Bs[kk*64 + tx*4];
            float a4[4] = {ar.x, ar.y, ar.z, ar.w};
            float b4[4] = {br.x, br.y, br.z, br.w};
            #pragma unroll
            for (int i = 0; i < 4; ++i)
                #pragma unroll
                for (int j = 0; j < 4; ++j)
                    acc[i][j] += a4[i] * b4[j];
        }
        __syncthreads();
    }

    if (nb < 12) {
        #pragma unroll
        for (int i = 0; i < 4; ++i) {
            int m = m0 + ty*4 + i;
            #pragma unroll
            for (int j = 0; j < 4; ++j)
                QKV[(size_t)m * RS + nb*64 + tx*4 + j] = acc[i][j];
        }
    } else {
        #pragma unroll
        for (int i = 0; i < 4; ++i) {
            int m = m0 + ty*4 + i;
            #pragma unroll
            for (int j = 0; j < 4; ++j) {
                int n = (nb - 12)*64 + tx*4 + j;
                float v = acc[i][j] + b1[n];
                v = 0.5f * v * (1.0f + erff(v * 0.70710678118654752440f));
                Hout[(size_t)m * 128 + n] = v;
            }
        }
    }
}

// ---------------- generic GEMM (MLP2, out-proj) ----------------
__global__ __launch_bounds__(256)
void gemm_kernel(const float* __restrict__ A, const float* __restrict__ B,
                 const float* __restrict__ bias, float* __restrict__ C,
                 int M, int N, int K)
{
    __shared__ float As[16*64];
    __shared__ float Bs[16*64];
    const int tid = threadIdx.x;
    const int tx = tid & 15, ty = tid >> 4;
    const int m0 = blockIdx.y * 64;
    const int n0 = blockIdx.x * 64;

    const int arow = tid >> 2, ak4 = (tid & 3) * 4;
    const int brow = tid >> 4, bn4 = (tid & 15) * 4;

    float acc[4][4] = {};
    float4 aPre = *(const float4*)&A[(size_t)(m0 + arow) * K + ak4];
    float4 bPre = make_float4(0.f,0.f,0.f,0.f);
    if (n0 + bn4 < N) bPre = *(const float4*)&B[(size_t)brow * N + n0 + bn4];

    for (int k0 = 0; k0 < K; k0 += 16) {
        As[(ak4+0)*64 + arow] = aPre.x;
        As[(ak4+1)*64 + arow] = aPre.y;
        As[(ak4+2)*64 + arow] = aPre.z;
        As[(ak4+3)*64 + arow] = aPre.w;
        *(float4*)&Bs[brow*64 + bn4] = bPre;
        __syncthreads();
        if (k0 + 16 < K) {
            aPre = *(const float4*)&A[(size_t)(m0 + arow) * K + k0 + 16 + ak4];
            if (n0 + bn4 < N) bPre = *(const float4*)&B[(size_t)(k0 + 16 + brow) * N + n0 + bn4];
        }
        #pragma unroll
        for (int kk = 0; kk < 16; ++kk) {
            float4 ar = *(const float4*)&As[kk*64 + ty*4];
            float4 br = *(const float4*)&Bs[kk*64 + tx*4];
            float a4[4] = {ar.x, ar.y, ar.z, ar.w};
            float b4[4] = {br.x, br.y, br.z, br.w};
            #pragma unroll
            for (int i = 0; i < 4; ++i)
                #pragma unroll
                for (int j = 0; j < 4; ++j)
                    acc[i][j] += a4[i] * b4[j];
        }
        __syncthreads();
    }

    #pragma unroll
    for (int i = 0; i < 4; ++i) {
        int m = m0 + ty*4 + i;
        #pragma unroll
        for (int j = 0; j < 4; ++j) {
            int n = n0 + tx*4 + j;
            if (n < N) C[(size_t)m * N + n] = acc[i][j] + bias[n];
        }
    }
}

// ---------------- fused deformable attention (tf32 MMA) ----------------
// smem: T[32][TP] | BUF(256*KSST, shared by K-tile / Vt-tile / reduction) | Qe[32][QEST] | wxs | rsum | axs
__global__ __launch_bounds__(256, 1)
void attn_kernel(const float* __restrict__ QKV, const float* __restrict__ OFF,
                 float* __restrict__ Aout)
{
    extern __shared__ float sm[];
    float* T    = sm;                       // 32*TP
    float* BUF  = T + QB*TP;                // 256*KSST floats
    float* Qe   = BUF + CT*KSST;            // 32*QEST
    float* wxs  = Qe + QB*QEST;
    float* rsum = wxs + QB;
    int*   axs  = (int*)(rsum + QB);

    const int tid = threadIdx.x;
    const int nq  = Ss / QB;
    const int bh  = blockIdx.x / nq;
    const int q0  = (blockIdx.x % nq) * QB;
    const int b   = bh / Hh;
    const int h   = bh % Hh;
    const float scale = 0.17677669529663689f;

    const float* Qb = QKV + (size_t)b*Ss*RS + h*Dd;
    const float* Kb = Qb + 256;
    const float* Vb = Qb + 512;

    const int lane = tid & 31;
    const int w    = tid >> 5;
    const int g    = lane >> 2;   // 0..7
    const int td   = lane & 3;    // 0..3

    // ---- Phase 0: Qeff (row-blended, pre-scaled) + wx/ax ----
    {
        const int d = tid & 31;
        const int qq = tid >> 5;
        #pragma unroll
        for (int it = 0; it < 4; ++it) {
            int q = qq + it*8;
            int i = q0 + q;
            float ox = OFF[((size_t)(b*Ss + i)*Hh + h)*2 + 0];
            float oy = OFF[((size_t)(b*Ss + i)*Hh + h)*2 + 1];
            float fy = floorf(oy);
            float wy = oy - fy;
            int y0 = i + (int)fy, y1 = y0 + 1;
            float qv = 0.f;
            if (y0 >= 0 && y0 < Ss) qv += (1.f - wy) * Qb[(size_t)y0*RS + d];
            if (y1 >= 0 && y1 < Ss) qv += wy * Qb[(size_t)y1*RS + d];
            Qe[q*QEST + d] = qv * scale;
            if (d == 0) { float fx = floorf(ox); wxs[q] = ox - fx; axs[q] = (int)fx; }
        }
    }
    __syncthreads();

    // ---- Phase 1: T = Qe . K^T via split-tf32 mma (M32 x N1024 x K32) ----
    {
        float4 pre[8];
        #pragma unroll
        for (int l = 0; l < 8; ++l) {
            int idx = tid + l*256;
            int c = idx >> 3, t = idx & 7;
            pre[l] = *(const float4*)&Kb[(size_t)c*RS + t*4];
        }
        for (int ct = 0; ct < Ss/CT; ++ct) {
            #pragma unroll
            for (int l = 0; l < 8; ++l) {
                int idx = tid + l*256;
                int c = idx >> 3, t = idx & 7;
                *(float4*)&BUF[c*KSST + t*4] = pre[l];
            }
            __syncthreads();
            if (ct + 1 < Ss/CT) {
                #pragma unroll
                for (int l = 0; l < 8; ++l) {
                    int idx = tid + l*256;
                    int c = idx >> 3, t = idx & 7;
                    pre[l] = *(const float4*)&Kb[(size_t)((ct+1)*CT + c)*RS + t*4];
                }
            }
            float acc[4][2][4];
            #pragma unroll
            for (int ng = 0; ng < 4; ++ng)
                #pragma unroll
                for (int m = 0; m < 2; ++m)
                    #pragma unroll
                    for (int r = 0; r < 4; ++r) acc[ng][m][r] = 0.f;

            #pragma unroll
            for (int ks = 0; ks < 4; ++ks) {
                unsigned ah[8], al[8];
                #pragma unroll
                for (int m = 0; m < 2; ++m) {
                    float a0 = Qe[(m*16 + g    )*QEST + ks*8 + td];
                    float a1 = Qe[(m*16 + g + 8)*QEST + ks*8 + td];
                    float a2 = Qe[(m*16 + g    )*QEST + ks*8 + td + 4];
                    float a3 = Qe[(m*16 + g + 8)*QEST + ks*8 + td + 4];
                    tf32split(a0, ah[m*4+0], al[m*4+0]);
                    tf32split(a1, ah[m*4+1], al[m*4+1]);
                    tf32split(a2, ah[m*4+2], al[m*4+2]);
                    tf32split(a3, ah[m*4+3], al[m*4+3]);
                }
                #pragma unroll
                for (int ng = 0; ng < 4; ++ng) {
                    int n0 = w*32 + ng*8;
                    float b0f = BUF[(n0 + g)*KSST + ks*8 + td];
                    float b1f = BUF[(n0 + g)*KSST + ks*8 + td + 4];
                    unsigned bh0, bl0, bh1, bl1;
                    tf32split(b0f, bh0, bl0);
                    tf32split(b1f, bh1, bl1);
                    #pragma unroll
                    for (int m = 0; m < 2; ++m) {
                        mma_tf32(acc[ng][m], ah + m*4, bh0, bh1);
                        mma_tf32(acc[ng][m], ah + m*4, bl0, bl1);
                        mma_tf32(acc[ng][m], al + m*4, bh0, bh1);
                    }
                }
            }
            #pragma unroll
            for (int ng = 0; ng < 4; ++ng) {
                int col = ct*CT + w*32 + ng*8 + 2*td;
                #pragma unroll
                for (int m = 0; m < 2; ++m) {
                    int r0 = m*16 + g;
                    *(float2*)&T[ r0     *TP + col] = make_float2(acc[ng][m][0], acc[ng][m][1]);
                    *(float2*)&T[(r0 + 8)*TP + col] = make_float2(acc[ng][m][2], acc[ng][m][3]);
                }
            }
            __syncthreads();
        }
    }

    // ---- Phase 2: shift/blend + softmax (warp per query) ----
    {
        #pragma unroll
        for (int it = 0; it < 4; ++it) {
            int q = w + it*8;
            float wx = wxs[q];
            int ax = axs[q];
            float* Tq = T + q*TP;
            float dv[32];
            float m = -1e30f;
            #pragma unroll
            for (int jj = 0; jj < 32; ++jj) {
                int j = lane + jj*32;
                int c0 = j + ax, c1 = c0 + 1;
                float t0 = (c0 >= 0 && c0 < Ss) ? Tq[c0] : 0.f;
                float t1 = (c1 >= 0 && c1 < Ss) ? Tq[c1] : 0.f;
                float v = (1.f - wx)*t0 + wx*t1;
                dv[jj] = v;
                m = fmaxf(m, v);
            }
            #pragma unroll
            for (int o = 16; o; o >>= 1) m = fmaxf(m, __shfl_xor_sync(0xffffffffu, m, o));
            float s = 0.f;
            #pragma unroll
            for (int jj = 0; jj < 32; ++jj) { float e = __expf(dv[jj] - m); dv[jj] = e; s += e; }
            #pragma unroll
            for (int o = 16; o; o >>= 1) s += __shfl_xor_sync(0xffffffffu, s, o);
            #pragma unroll
            for (int jj = 0; jj < 32; ++jj) Tq[lane + jj*32] = dv[jj];
            if (lane == 0) rsum[q] = s;
        }
    }
    __syncthreads();

    // ---- Phase 3: out = P.V via split-tf32 mma (M32 x N32 x K1024, K split over warps) ----
    {
        float acc[4][2][4];
        #pragma unroll
        for (int ng = 0; ng < 4; ++ng)
            #pragma unroll
            for (int m = 0; m < 2; ++m)
                #pragma unroll
                for (int r = 0; r < 4; ++r) acc[ng][m][r] = 0.f;

        float4 pre[8];
        #pragma unroll
        for (int l = 0; l < 8; ++l) {
            int idx = tid + l*256;
            int c = idx >> 3, t = idx & 7;
            pre[l] = *(const float4*)&Vb[(size_t)c*RS + t*4];
        }
        for (int jt = 0; jt < Ss/CT; ++jt) {
            // stage transposed V tile: Vt[d][c]
            #pragma unroll
            for (int l = 0; l < 8; ++l) {
                int idx = tid + l*256;
                int c = idx >> 3, t = idx & 7;
                BUF[(t*4+0)*VTST + c] = pre[l].x;
                BUF[(t*4+1)*VTST + c] = pre[l].y;
                BUF[(t*4+2)*VTST + c] = pre[l].z;
                BUF[(t*4+3)*VTST + c] = pre[l].w;
            }
            __syncthreads();
            if (jt + 1 < Ss/CT) {
                #pragma unroll
                for (int l = 0; l < 8; ++l) {
                    int idx = tid + l*256;
                    int c = idx >> 3, t = idx & 7;
                    pre[l] = *(const float4*)&Vb[(size_t)((jt+1)*CT + c)*RS + t*4];
                }
            }
            #pragma unroll
            for (int ks = 0; ks < 4; ++ks) {
                int cbase = jt*CT + w*32 + ks*8;
                int clocal = w*32 + ks*8;
                unsigned ah[8], al[8];
                #pragma unroll
                for (int m = 0; m < 2; ++m) {
                    float a0 = T[(m*16 + g    )*TP + cbase + td];
                    float a1 = T[(m*16 + g + 8)*TP + cbase + td];
                    float a2 = T[(m*16 + g    )*TP + cbase + td + 4];
                    float a3 = T[(m*16 + g + 8)*TP + cbase + td + 4];
                    tf32split(a0, ah[m*4+0], al[m*4+0]);
                    tf32split(a1, ah[m*4+1], al[m*4+1]);
                    tf32split(a2, ah[m*4+2], al[m*4+2]);
                    tf32split(a3, ah[m*4+3], al[m*4+3]);
                }
                #pragma unroll
                for (int ng = 0; ng < 4; ++ng) {
                    float b0f = BUF[(ng*8 + g)*VTST + clocal + td];
                    float b1f = BUF[(ng*8 + g)*VTST + clocal + td + 4];
                    unsigned bh0, bl0, bh1, bl1;
                    tf32split(b0f, bh0, bl0);
                    tf32split(b1f, bh1, bl1);
                    #pragma unroll
                    for (int m = 0; m < 2; ++m) {
                        mma_tf32(acc[ng][m], ah + m*4, bh0, bh1);
                        mma_tf32(acc[ng][m], ah + m*4, bl0, bl1);
                        mma_tf32(acc[ng][m], al + m*4, bh0, bh1);
                    }
                }
            }
            __syncthreads();
        }
        // write per-warp partials into BUF (now free) and reduce
        #pragma unroll
        for (int ng = 0; ng < 4; ++ng) {
            int dcol = ng*8 + 2*td;
            #pragma unroll
            for (int m = 0; m < 2; ++m) {
                int r0 = m*16 + g;
                BUF[w*REDW +  r0     *33 + dcol    ] = acc[ng][m][0];
                BUF[w*REDW +  r0     *33 + dcol + 1] = acc[ng][m][1];
                BUF[w*REDW + (r0 + 8)*33 + dcol    ] = acc[ng][m][2];
                BUF[w*REDW + (r0 + 8)*33 + dcol + 1] = acc[ng][m][3];
            }
        }
        __syncthreads();
        for (int r = tid; r < QB*Dd; r += 256) {
            int q = r >> 5, d = r & 31;
            float s = 0.f;
            #pragma unroll
            for (int wv = 0; wv < 8; ++wv) s += BUF[wv*REDW + q*33 + d];
            int i = q0 + q;
            Aout[((size_t)b*Ss + i)*Ee + h*Dd + d] = s / rsum[q];
        }
    }
}

// ---------------- host launch ----------------
extern "C" void kernel_launch(void* const* d_in, const int* in_sizes, int n_in,
                              void* d_out, int out_size)
{
    (void)in_sizes; (void)n_in; (void)out_size;
    const float* x      = (const float*)d_in[0];
    const float* Wq     = (const float*)d_in[1];
    const float* Wk     = (const float*)d_in[2];
    const float* Wv     = (const float*)d_in[3];
    const float* W_off1 = (const float*)d_in[4];
    const float* b_off1 = (const float*)d_in[5];
    const float* W_off2 = (const float*)d_in[6];
    const float* b_off2 = (const float*)d_in[7];
    const float* W_out  = (const float*)d_in[8];
    const float* b_out  = (const float*)d_in[9];
    float* out = (float*)d_out;

    float *gQKV, *gH, *gO, *gA;
    cudaGetSymbolAddress((void**)&gQKV, g_QKV);
    cudaGetSymbolAddress((void**)&gH,   g_H);
    cudaGetSymbolAddress((void**)&gO,   g_O);
    cudaGetSymbolAddress((void**)&gA,   g_A);

    const int attn_smem = (QB*TP + CT*KSST + QB*QEST + QB + QB + QB) * (int)sizeof(float);
    cudaFuncSetAttribute(attn_kernel, cudaFuncAttributeMaxDynamicSharedMemorySize, attn_smem);

    dim3 blk(256);

    qkv_mlp_kernel<<<dim3(14, TOK/64), blk>>>(x, Wq, Wk, Wv, W_off1, b_off1, gQKV, gH);
    gemm_kernel<<<dim3(1, TOK/64), blk>>>(gH, W_off2, b_off2, gO, TOK, 2*Hh, Ee/2);
    attn_kernel<<<Bb*Hh*(Ss/QB), blk, attn_smem>>>(gQKV, gO, gA);
    gemm_kernel<<<dim3(4, TOK/64), blk>>>(gA, W_out, b_out, out, TOK, Ee, Ee);
}